// round 1
// baseline (speedup 1.0000x reference)
#include <cuda_runtime.h>
#include <cuda_bf16.h>

// Fused preprocessing:
//   x = images * (1/255)
//   x = bilinear_resize(x, 1280x960 -> 640x640, half-pixel centers, no AA)
//   x = (x - mean) / std
//   out = NHWC -> NCHW
//
// Exploits: vertical scale == 2.0 exactly -> frac always 0.5 (rows 2y, 2y+1).
// Horizontal scale == 1.5 -> even x: cols (3k,3k+1) w=0.25; odd x: cols
// (3k+1,3k+2) w=0.75. No boundary clamping is ever required for these shapes.
// Normalization + rescale fold into one per-channel FMA; the 3 reciprocals
// are computed once per block (per-thread divides would be MUFU-bound).

#define IN_H 1280
#define IN_W 960
#define OUT_H 640
#define OUT_W 640
#define CH 3

__global__ __launch_bounds__(128) void preproc_kernel(
    const float* __restrict__ img,   // [B, 1280, 960, 3]
    const float* __restrict__ mean,  // [3]
    const float* __restrict__ stdv,  // [3]
    float* __restrict__ out)         // [B, 3, 640, 640]
{
    __shared__ float s_scale[CH];
    __shared__ float s_bias[CH];
    const int tx = threadIdx.x;
    if (tx < CH) {
        float inv = 1.0f / stdv[tx];
        s_scale[tx] = (1.0f / 255.0f) * inv;
        s_bias[tx]  = -mean[tx] * inv;
    }
    __syncthreads();

    const int x = blockIdx.x * 128 + tx;   // 0..639
    const int y = blockIdx.y;              // 0..639
    const int b = blockIdx.z;              // 0..15

    // Horizontal source position: sx = 1.5x + 0.25
    const int  k   = x >> 1;
    const int  odd = x & 1;
    const int  ix  = 3 * k + odd;               // left source column
    const float fx = odd ? 0.75f : 0.25f;

    // Vertical: rows 2y and 2y+1, weights 0.5/0.5
    const int r0 = 2 * y;
    const float* __restrict__ row0 = img + ((b * IN_H + r0) * IN_W + ix) * CH;
    const float* __restrict__ row1 = row0 + IN_W * CH;

    // 4 source pixels x 3 channels
    float p00[CH], p01[CH], p10[CH], p11[CH];
#pragma unroll
    for (int c = 0; c < CH; ++c) {
        p00[c] = __ldg(row0 + c);
        p01[c] = __ldg(row0 + CH + c);
        p10[c] = __ldg(row1 + c);
        p11[c] = __ldg(row1 + CH + c);
    }

    const int obase = (b * CH) * (OUT_H * OUT_W) + y * OUT_W + x;
#pragma unroll
    for (int c = 0; c < CH; ++c) {
        float top = fmaf(p01[c] - p00[c], fx, p00[c]);
        float bot = fmaf(p11[c] - p10[c], fx, p10[c]);
        float v   = 0.5f * (top + bot);
        out[obase + c * (OUT_H * OUT_W)] = fmaf(v, s_scale[c], s_bias[c]);
    }
}

extern "C" void kernel_launch(void* const* d_in, const int* in_sizes, int n_in,
                              void* d_out, int out_size) {
    const float* img  = (const float*)d_in[0];
    const float* mean = (const float*)d_in[1];
    const float* stdv = (const float*)d_in[2];
    float* out = (float*)d_out;

    dim3 block(128, 1, 1);
    dim3 grid(OUT_W / 128, OUT_H, 16);   // (5, 640, 16)
    preproc_kernel<<<grid, block>>>(img, mean, stdv, out);
}

// round 4
// speedup vs baseline: 1.0807x; 1.0807x over previous
#include <cuda_runtime.h>
#include <cuda_bf16.h>

// Fused preprocessing: rescale(1/255) -> bilinear 1280x960 -> 640x640
// (half-pixel centers) -> normalize -> NHWC->NCHW.
//
// Structure: vertical scale is exactly 2.0 (frac always 0.5), so each output
// row is the plain average of input rows 2y and 2y+1. One block per
// (output row, batch):
//   stage: float4-coalesced loads of both input rows, averaged in registers,
//          ONE averaged row (2880 floats) written to smem.
//   compute: each of 160 threads produces 4 consecutive output px from 18
//          contiguous smem floats, applies folded rescale+normalize FMA, and
//          writes one float4 per channel plane (coalesced STG.128).
// Horizontal: src_x = 1.5x + 0.25 -> px group {4t..4t+3} uses input cols
// {6t..6t+5} with fracs {.25,.75,.25,.75}. No clamping needed at these shapes.

#define IN_H    1280
#define IN_W    960
#define OUT_HW  640
#define ROW_F   (IN_W * 3)     // 2880 floats per input row
#define ROW_F4  (ROW_F / 4)    // 720 float4
#define NT      240            // 720 float4 / 240 = 3 staging iters
#define PLANE   (OUT_HW * OUT_HW)

__global__ __launch_bounds__(NT) void preproc_kernel(
    const float* __restrict__ img,   // [16, 1280, 960, 3]
    const float* __restrict__ mean,  // [3]
    const float* __restrict__ stdv,  // [3]
    float* __restrict__ out)         // [16, 3, 640, 640]
{
    __shared__ float s_row[ROW_F];      // vertically averaged input row
    __shared__ float s_scale[3];
    __shared__ float s_bias[3];

    const int t = threadIdx.x;
    if (t < 3) {
        const float inv = 1.0f / stdv[t];
        s_scale[t] = (1.0f / 255.0f) * inv;
        s_bias[t]  = -mean[t] * inv;
    }

    const int y = blockIdx.x;   // 0..639
    const int b = blockIdx.y;   // 0..15

    // ---- stage: rows 2y, 2y+1 -> averaged row in smem (float4 coalesced) ----
    const float4* __restrict__ r0 =
        (const float4*)(img + (size_t)(b * IN_H + 2 * y) * ROW_F);
    const float4* __restrict__ r1 = r0 + ROW_F4;
    float4* s4 = (float4*)s_row;
#pragma unroll
    for (int j = 0; j < 3; ++j) {
        const int idx = t + j * NT;
        float4 a = __ldg(&r0[idx]);
        float4 c = __ldg(&r1[idx]);
        float4 m;
        m.x = 0.5f * (a.x + c.x);
        m.y = 0.5f * (a.y + c.y);
        m.z = 0.5f * (a.z + c.z);
        m.w = 0.5f * (a.w + c.w);
        s4[idx] = m;
    }
    __syncthreads();

    // ---- compute: 4 output px per thread, threads 0..159 ----
    if (t < 160) {
        float v[18];
        const float2* sp = (const float2*)&s_row[18 * t];  // 8B-aligned (t*72B)
#pragma unroll
        for (int j = 0; j < 9; ++j) {
            float2 p = sp[j];
            v[2 * j]     = p.x;
            v[2 * j + 1] = p.y;
        }

        const int ob = b * 3 * PLANE + y * OUT_HW + 4 * t;
#pragma unroll
        for (int c = 0; c < 3; ++c) {
            const float a0 = v[c],      a1 = v[3 + c],  a2 = v[6 + c];
            const float a3 = v[9 + c],  a4 = v[12 + c], a5 = v[15 + c];
            float4 o;
            o.x = fmaf(a1 - a0, 0.25f, a0);   // x = 4t   (even, fx=.25)
            o.y = fmaf(a2 - a1, 0.75f, a1);   // x = 4t+1 (odd,  fx=.75)
            o.z = fmaf(a4 - a3, 0.25f, a3);   // x = 4t+2
            o.w = fmaf(a5 - a4, 0.75f, a4);   // x = 4t+3
            const float sc = s_scale[c], bi = s_bias[c];
            o.x = fmaf(o.x, sc, bi);
            o.y = fmaf(o.y, sc, bi);
            o.z = fmaf(o.z, sc, bi);
            o.w = fmaf(o.w, sc, bi);
            *(float4*)&out[ob + c * PLANE] = o;
        }
    }
}

extern "C" void kernel_launch(void* const* d_in, const int* in_sizes, int n_in,
                              void* d_out, int out_size) {
    const float* img  = (const float*)d_in[0];
    const float* mean = (const float*)d_in[1];
    const float* stdv = (const float*)d_in[2];
    float* out = (float*)d_out;

    dim3 block(NT, 1, 1);
    dim3 grid(OUT_HW, 16, 1);   // (640 rows, 16 batches)
    preproc_kernel<<<grid, block>>>(img, mean, stdv, out);
}